// round 7
// baseline (speedup 1.0000x reference)
#include <cuda_runtime.h>

#define BATCH 2
#define NBOX  1000
#define NCLS  80
#define NCAND 100
#define CAND  2048          // max candidates per batch (hard cap)
#define STAGE_CAP 32768     // hard bound: <=32 classes/box with p>=1/32
#define NHIST 4096
#define TARGET 1200
#define PC 0.03125f         // stage only p >= 1/32 (bucket-aligned)

typedef unsigned long long u64;
typedef unsigned int u32;

__device__ u32 g_hist[BATCH * NHIST];   // zero-init at load; self-cleaned
__device__ int g_scnt[BATCH];
__device__ u64 g_stage[BATCH * STAGE_CAP];

// dynamic smem layout for nms_final_kernel (bytes)
#define SK_KEYS 0                 // 2048 u64   (16384)
#define SK_BOX  16384             // 2048 float4 (32768)
#define SK_SUPP 49152             // 2048 u8
#define SK_SEG  51200             // 81 int (324 -> pad 384)
#define SK_WARP 51584             // 32 u32 warp totals
#define SK_CEXC 51712             // 32 u32 coarse exclusive suffix
#define SK_TOTAL 51840

// ---------------------------------------------------------------------------
// Kernel 1: single-pass softmax; stage keys for p >= PC; histogram.
// One warp per (b, n). 250 blocks x 256.
// ---------------------------------------------------------------------------
__global__ void score_kernel(const float* __restrict__ cls) {
    int gw   = (blockIdx.x * blockDim.x + threadIdx.x) >> 5;
    int lane = threadIdx.x & 31;
    if (gw >= BATCH * NBOX) return;
    int b = gw / NBOX, n = gw % NBOX;

    const float* lg = cls + (size_t)(b * NBOX + n) * 81;

    // one read pass: lane owns logit indices lane, lane+32, lane+64
    float v0 = lg[lane];
    float v1 = lg[lane + 32];
    bool  ok2 = (lane + 64) < 81;
    float v2 = ok2 ? lg[lane + 64] : -1e30f;

    float mx = fmaxf(fmaxf(v0, v1), v2);
    #pragma unroll
    for (int o = 16; o; o >>= 1) mx = fmaxf(mx, __shfl_xor_sync(0xffffffffu, mx, o));

    float e0 = expf(v0 - mx);
    float e1 = expf(v1 - mx);
    float e2 = ok2 ? expf(v2 - mx) : 0.f;

    float s = e0 + e1 + e2;
    #pragma unroll
    for (int o = 16; o; o >>= 1) s += __shfl_xor_sync(0xffffffffu, s, o);
    float inv = 1.f / s;

    float pr[3] = { e0 * inv, e1 * inv, e2 * inv };

    #pragma unroll
    for (int h = 0; h < 3; h++) {
        int idx = lane + 32 * h;                 // logit index 0..80
        float p = pr[h];
        bool pred = (idx >= 1) && (idx <= 80) && (p >= PC);
        u32 m = __ballot_sync(0xffffffffu, pred);
        if (m) {
            int leader = __ffs(m) - 1;
            u32 base = 0;
            if (lane == leader) base = (u32)atomicAdd(&g_scnt[b], (int)__popc(m));
            base = __shfl_sync(0xffffffffu, base, leader);
            if (pred) {
                u32 sb = __float_as_uint(p);
                int c = idx - 1;
                u64 key = ((u64)(u32)(79 - c) << 42) | ((u64)sb << 10)
                        | (u64)(u32)(1023 - n);
                g_stage[b * STAGE_CAP + base + __popc(m & ((1u << lane) - 1u))] = key;
                atomicAdd(&g_hist[b * NHIST + (sb >> 19)], 1u);
            }
        }
    }
}

// ---------------------------------------------------------------------------
// Hybrid bitonic sort of 2048 u64 keys, descending. 1024 threads; thread t
// owns elements t and t+1024. smem only for j>=32 stages. Ends stored+synced.
// ---------------------------------------------------------------------------
__device__ __forceinline__ u64 cmpsel(u64 v, u64 pv, bool keep_max) {
    return keep_max ? (v >= pv ? v : pv) : (v <= pv ? v : pv);
}

__device__ void sort2048_desc(u64* s, int t) {
    u64 v0 = s[t];
    u64 v1 = s[t + 1024];

    for (unsigned k = 2; k <= 1024; k <<= 1) {
        bool dir0 = ((t & (int)k) == 0);
        bool dir1 = (k == 1024) ? false : dir0;
        unsigned j = k >> 1;
        for (; j >= 32; j >>= 1) {
            s[t] = v0; s[t + 1024] = v1;
            __syncthreads();
            u64 p0 = s[t ^ (int)j];
            u64 p1 = s[(t ^ (int)j) + 1024];
            __syncthreads();
            bool side = ((t & (int)j) == 0);
            v0 = cmpsel(v0, p0, side == dir0);
            v1 = cmpsel(v1, p1, side == dir1);
        }
        #pragma unroll
        for (unsigned jj = 16; jj >= 1; jj >>= 1) {
            if (jj <= j) {
                u64 p0 = __shfl_xor_sync(0xffffffffu, v0, jj);
                u64 p1 = __shfl_xor_sync(0xffffffffu, v1, jj);
                bool side = ((t & (int)jj) == 0);
                v0 = cmpsel(v0, p0, side == dir0);
                v1 = cmpsel(v1, p1, side == dir1);
            }
        }
    }
    if (v0 < v1) { u64 tmp = v0; v0 = v1; v1 = tmp; }
    for (unsigned j = 512; j >= 32; j >>= 1) {
        s[t] = v0; s[t + 1024] = v1;
        __syncthreads();
        u64 p0 = s[t ^ (int)j];
        u64 p1 = s[(t ^ (int)j) + 1024];
        __syncthreads();
        bool side = ((t & (int)j) == 0);
        v0 = cmpsel(v0, p0, side);
        v1 = cmpsel(v1, p1, side);
    }
    #pragma unroll
    for (unsigned jj = 16; jj >= 1; jj >>= 1) {
        u64 p0 = __shfl_xor_sync(0xffffffffu, v0, jj);
        u64 p1 = __shfl_xor_sync(0xffffffffu, v1, jj);
        bool side = ((t & (int)jj) == 0);
        v0 = cmpsel(v0, p0, side);
        v1 = cmpsel(v1, p1, side);
    }
    s[t] = v0; s[t + 1024] = v1;
    __syncthreads();
}

// ---------------------------------------------------------------------------
// Kernel 2: per batch — threshold, filter, sort, decode, NMS, top-100.
// grid = 2, block = 1024.
// ---------------------------------------------------------------------------
__global__ __launch_bounds__(1024) void nms_final_kernel(
        const float* __restrict__ box,
        const float* __restrict__ anc,
        const float* __restrict__ info,
        float* __restrict__ out) {
    extern __shared__ unsigned char sm[];
    u64*           keys = (u64*)   (sm + SK_KEYS);
    float4*        sbox = (float4*)(sm + SK_BOX);
    unsigned char* supp = (unsigned char*)(sm + SK_SUPP);
    int*           seg  = (int*)   (sm + SK_SEG);
    u32*           wtot = (u32*)   (sm + SK_WARP);
    u32*           cexc = (u32*)   (sm + SK_CEXC);

    __shared__ int sm_cnt, sm_t1, sm_t2, sm_tb, sm_M;

    int tid  = threadIdx.x;
    int w    = tid >> 5;
    int lane = tid & 31;
    int b    = blockIdx.x;

    if (tid == 0) { sm_cnt = 0; sm_t1 = 0; sm_t2 = NHIST - 1; }
    __syncthreads();

    // ---- phase 0: hierarchical suffix scan of score-bit histogram ----
    u32 h0 = g_hist[b * NHIST + 4 * tid + 0];
    u32 h1 = g_hist[b * NHIST + 4 * tid + 1];
    u32 h2 = g_hist[b * NHIST + 4 * tid + 2];
    u32 h3 = g_hist[b * NHIST + 4 * tid + 3];
    u32 s3 = h3, s2 = h2 + s3, s1 = h1 + s2, s0 = h0 + s1;

    // warp inclusive suffix of s0
    u32 x = s0;
    #pragma unroll
    for (int off = 1; off < 32; off <<= 1) {
        u32 t = __shfl_down_sync(0xffffffffu, x, off);
        if (lane + off < 32) x += t;
    }
    if (lane == 0) wtot[w] = x;          // warp total
    __syncthreads();
    if (w == 0) {
        u32 y = wtot[lane];
        u32 yi = y;
        #pragma unroll
        for (int off = 1; off < 32; off <<= 1) {
            u32 t = __shfl_down_sync(0xffffffffu, yi, off);
            if (lane + off < 32) yi += t;
        }
        cexc[lane] = yi - y;             // suffix over warps > this one
    }
    __syncthreads();
    {
        u32 tail = (x - s0) + cexc[w];   // suffix strictly after this group
        u32 suf[4] = { s0 + tail, s1 + tail, s2 + tail, s3 + tail };
        #pragma unroll
        for (int q = 0; q < 4; q++) {
            int v = 4 * tid + q;
            if (suf[q] >= TARGET) atomicMax(&sm_t1, v);
            if (suf[q] <= CAND)   atomicMin(&sm_t2, v);
        }
    }
    __syncthreads();
    if (tid == 0) sm_tb = (sm_t1 > sm_t2) ? sm_t1 : sm_t2;
    __syncthreads();

    // ---- phase 1: filter staged keys (warp-aggregated push) ----
    int Ms = g_scnt[b];
    u32 tb = (u32)sm_tb;
    int iters = (Ms + 1023) >> 10;
    for (int it = 0; it < iters; it++) {
        int i = it * 1024 + tid;
        u64 k = 0ull;
        bool pred = false;
        if (i < Ms) {
            k = g_stage[b * STAGE_CAP + i];
            pred = (((u32)(k >> 10)) >> 19) >= tb;
        }
        u32 m = __ballot_sync(0xffffffffu, pred);
        if (m) {
            int leader = __ffs(m) - 1;
            int base = 0;
            if (lane == leader) base = atomicAdd(&sm_cnt, (int)__popc(m));
            base = __shfl_sync(0xffffffffu, base, leader);
            if (pred)
                keys[base + __popc(m & ((1u << lane) - 1u))] = k;  // <= CAND guaranteed
        }
    }
    __syncthreads();
    int M = sm_cnt;
    if (tid == 0) sm_M = M;
    for (int i = tid; i < CAND; i += 1024) if (i >= M) keys[i] = 0ull;
    __syncthreads();

    // ---- phase 2: sort by (class asc, score desc, idx asc) ----
    sort2048_desc(keys, tid);

    // ---- phase 3: class segment starts ----
    if (tid <= NCLS) seg[tid] = M;
    __syncthreads();
    for (int i = tid; i < CAND; i += 1024) {
        if (i < M) {
            int ci = 79 - (int)(keys[i] >> 42);
            int cp = (i == 0) ? -1 : (79 - (int)(keys[i - 1] >> 42));
            for (int cc = cp + 1; cc <= ci; cc++) seg[cc] = i;
        }
    }
    __syncthreads();

    // ---- phase 4: decode candidate boxes ----
    float hmax = info[b * 5 + 0] - 1.f;
    float wmax = info[b * 5 + 1] - 1.f;
    for (int i = tid; i < CAND; i += 1024) {
        if (i < M) {
            u64 k = keys[i];
            int c = 79 - (int)(k >> 42);
            int n = 1023 - (int)(k & 0x3FFull);
            float4 a = *(const float4*)(anc + (size_t)(b * NBOX + n) * 4);
            float ha  = a.z - a.x + 1.f;
            float wa  = a.w - a.y + 1.f;
            float cya = a.x + 0.5f * ha;
            float cxa = a.y + 0.5f * wa;
            float4 e = *(const float4*)(box +
                         ((size_t)(b * NBOX + n) * 81 + (c + 1)) * 4);
            float cy = (e.x / 10.f) * ha + cya;
            float cx = (e.y / 10.f) * wa + cxa;
            float h  = expf(e.z / 5.f) * ha;
            float wd = expf(e.w / 5.f) * wa;
            float ymin = fminf(fmaxf(cy - 0.5f * h,        0.f), hmax);
            float ymax = fminf(fmaxf(cy + 0.5f * h - 1.f,  0.f), hmax);
            float xmin = fminf(fmaxf(cx - 0.5f * wd,       0.f), wmax);
            float xmax = fminf(fmaxf(cx + 0.5f * wd - 1.f, 0.f), wmax);
            sbox[i] = make_float4(ymin, xmin, ymax, xmax);
            supp[i] = 0;
        }
    }
    __syncthreads();

    // ---- phase 5: greedy NMS, one warp per class ----
    for (int c = w; c < NCLS; c += 32) {
        int s0i = seg[c];
        int n   = seg[c + 1] - s0i;
        for (int i = 0; i < n - 1; i++) {
            bool alive = (supp[s0i + i] == 0);       // uniform read
            if (alive) {
                float4 B = sbox[s0i + i];
                float ai = (B.z - B.x) * (B.w - B.y);
                for (int j = i + 1 + lane; j < n; j += 32) {
                    float4 C = sbox[s0i + j];
                    float iy = fmaxf(0.f, fminf(B.z, C.z) - fmaxf(B.x, C.x));
                    float ix = fmaxf(0.f, fminf(B.w, C.w) - fmaxf(B.y, C.y));
                    float inter = iy * ix;
                    float aj  = (C.z - C.x) * (C.w - C.y);
                    float iou = inter / fmaxf(ai + aj - inter, 1e-8f);
                    if (iou > 0.5f) supp[s0i + j] = 1;
                }
            }
            __syncwarp();
        }
    }
    __syncthreads();

    // ---- phase 6: survivor keys (score desc, flat idx asc), sort ----
    M = sm_M;
    for (int i = tid; i < CAND; i += 1024) {
        u64 nk = 0ull;
        if (i < M && supp[i] == 0) {
            u64 k = keys[i];
            int c = 79 - (int)(k >> 42);
            u32 sb = (u32)(k >> 10);
            u32 flat = (u32)(c * 2048 + (i - seg[c]));   // rank == true class rank
            nk = ((u64)sb << 18) | (u64)(0x3FFFFu ^ flat);
        }
        keys[i] = nk;
    }
    __syncthreads();
    sort2048_desc(keys, tid);

    // ---- phase 7: emit top-100 detections ----
    if (tid < NCAND) {
        u64 kv   = keys[tid];
        u32 sb   = (u32)(kv >> 18);
        u32 flat = 0x3FFFFu ^ ((u32)kv & 0x3FFFFu);
        int c    = (int)(flat >> 11);
        int slot = seg[c] + (int)(flat & 0x7FFu);
        float4 bx = sbox[slot];
        float* o = out + (size_t)(b * NCAND + tid) * 6;
        o[0] = bx.x; o[1] = bx.y; o[2] = bx.z; o[3] = bx.w;
        o[4] = __uint_as_float(sb);
        o[5] = (float)(c + 1);
    }

    // ---- cleanup: restore globals for the next invocation ----
    for (int i = tid; i < NHIST; i += 1024) g_hist[b * NHIST + i] = 0;
    if (tid == 0) g_scnt[b] = 0;
}

// ---------------------------------------------------------------------------
extern "C" void kernel_launch(void* const* d_in, const int* in_sizes, int n_in,
                              void* d_out, int out_size) {
    const float* cls  = (const float*)d_in[0];
    const float* box  = (const float*)d_in[1];
    const float* anc  = (const float*)d_in[2];
    const float* info = (const float*)d_in[3];

    cudaFuncSetAttribute(nms_final_kernel,
                         cudaFuncAttributeMaxDynamicSharedMemorySize, SK_TOTAL);

    score_kernel<<<(BATCH * NBOX * 32 + 255) / 256, 256>>>(cls);
    nms_final_kernel<<<BATCH, 1024, SK_TOTAL>>>(box, anc, info, (float*)d_out);
}

// round 8
// speedup vs baseline: 1.9403x; 1.9403x over previous
#include <cuda_runtime.h>

#define BATCH 2
#define NBOX  1000
#define NCLS  80
#define NCAND 100
#define CAND  2048          // max filtered candidates per batch
#define BCAP  1024          // per-class staging capacity (<=1000 used)
#define NHIST 4096
#define TARGET 1200
#define PC 0.03125f         // stage only p >= 1/32 (bucket-aligned)

typedef unsigned long long u64;
typedef unsigned int u32;

// globals zero-initialized at load; each invocation self-cleans.
__device__ int    g_bcnt[BATCH * NCLS];            // per-class staged counts
__device__ u64    g_bstage[BATCH * NCLS * BCAP];   // per-class staged keys
__device__ u32    g_hist [BATCH * NHIST];          // candidate score histogram
__device__ u32    g_hist2[BATCH * NHIST];          // survivor score histogram
__device__ u32    g_tb[BATCH];                     // candidate threshold bucket
__device__ int    g_scnt2[BATCH];                  // survivor counts
__device__ u64    g_surv[BATCH * CAND];            // survivor keys
__device__ float4 g_cbox[BATCH * NCLS * BCAP];     // survivor boxes by (c, rank)

// ---------------------------------------------------------------------------
// K1: single-pass softmax; stage (score, ~boxidx) into per-class buckets;
// histogram score bits. One warp per (b, n). 250 blocks x 256.
// ---------------------------------------------------------------------------
__global__ void score_kernel(const float* __restrict__ cls) {
    int gw   = (blockIdx.x * blockDim.x + threadIdx.x) >> 5;
    int lane = threadIdx.x & 31;
    if (gw >= BATCH * NBOX) return;
    int b = gw / NBOX, n = gw % NBOX;

    const float* lg = cls + (size_t)(b * NBOX + n) * 81;

    float v0 = lg[lane];
    float v1 = lg[lane + 32];
    bool  ok2 = (lane + 64) < 81;
    float v2 = ok2 ? lg[lane + 64] : -1e30f;

    float mx = fmaxf(fmaxf(v0, v1), v2);
    #pragma unroll
    for (int o = 16; o; o >>= 1) mx = fmaxf(mx, __shfl_xor_sync(0xffffffffu, mx, o));

    float e0 = expf(v0 - mx);
    float e1 = expf(v1 - mx);
    float e2 = ok2 ? expf(v2 - mx) : 0.f;

    float s = e0 + e1 + e2;
    #pragma unroll
    for (int o = 16; o; o >>= 1) s += __shfl_xor_sync(0xffffffffu, s, o);
    float inv = 1.f / s;

    float pr[3] = { e0 * inv, e1 * inv, e2 * inv };

    #pragma unroll
    for (int h = 0; h < 3; h++) {
        int idx = lane + 32 * h;                 // logit index 0..80
        float p = pr[h];
        if (idx >= 1 && idx <= 80 && p >= PC) {
            u32 sb = __float_as_uint(p);
            int ci = b * NCLS + (idx - 1);
            int pos = atomicAdd(&g_bcnt[ci], 1);  // < 1000 always
            g_bstage[(size_t)ci * BCAP + pos] = ((u64)sb << 10) | (u32)(1023 - n);
            atomicAdd(&g_hist[b * NHIST + (sb >> 19)], 1u);
        }
    }
}

// ---------------------------------------------------------------------------
// K2: per batch — threshold bucket from histogram suffix counts; clean hist.
// grid = BATCH, block = 1024.
// ---------------------------------------------------------------------------
__global__ __launch_bounds__(1024) void thresh_kernel() {
    __shared__ u32 wtot[32], cexc[32];
    __shared__ int sm_t1, sm_t2;

    int tid  = threadIdx.x;
    int w    = tid >> 5;
    int lane = tid & 31;
    int b    = blockIdx.x;

    if (tid == 0) { sm_t1 = 0; sm_t2 = NHIST - 1; }
    __syncthreads();

    u32 h0 = g_hist[b * NHIST + 4 * tid + 0];
    u32 h1 = g_hist[b * NHIST + 4 * tid + 1];
    u32 h2 = g_hist[b * NHIST + 4 * tid + 2];
    u32 h3 = g_hist[b * NHIST + 4 * tid + 3];
    u32 s3 = h3, s2 = h2 + s3, s1 = h1 + s2, s0 = h0 + s1;

    u32 x = s0;
    #pragma unroll
    for (int off = 1; off < 32; off <<= 1) {
        u32 t = __shfl_down_sync(0xffffffffu, x, off);
        if (lane + off < 32) x += t;
    }
    if (lane == 0) wtot[w] = x;
    __syncthreads();
    if (w == 0) {
        u32 y = wtot[lane];
        u32 yi = y;
        #pragma unroll
        for (int off = 1; off < 32; off <<= 1) {
            u32 t = __shfl_down_sync(0xffffffffu, yi, off);
            if (lane + off < 32) yi += t;
        }
        cexc[lane] = yi - y;
    }
    __syncthreads();
    {
        u32 tail = (x - s0) + cexc[w];
        u32 suf[4] = { s0 + tail, s1 + tail, s2 + tail, s3 + tail };
        #pragma unroll
        for (int q = 0; q < 4; q++) {
            int v = 4 * tid + q;
            if (suf[q] >= TARGET) atomicMax(&sm_t1, v);
            if (suf[q] <= CAND)   atomicMin(&sm_t2, v);
        }
    }
    __syncthreads();
    if (tid == 0) g_tb[b] = (u32)((sm_t1 > sm_t2) ? sm_t1 : sm_t2);

    // clean candidate histogram for next invocation
    g_hist[b * NHIST + 4 * tid + 0] = 0;
    g_hist[b * NHIST + 4 * tid + 1] = 0;
    g_hist[b * NHIST + 4 * tid + 2] = 0;
    g_hist[b * NHIST + 4 * tid + 3] = 0;
}

// ---------------------------------------------------------------------------
// K3: per (b, class) — filter, sort, decode, greedy NMS, emit survivors.
// grid = BATCH*NCLS, block = 128.
// ---------------------------------------------------------------------------
__global__ __launch_bounds__(128) void class_nms_kernel(
        const float* __restrict__ box,
        const float* __restrict__ anc,
        const float* __restrict__ info) {
    __shared__ u64 skey[BCAP];
    __shared__ float4 sbx[BCAP];
    __shared__ unsigned char sflag[BCAP];
    __shared__ int s_n, s_cnt, s_base;

    int tid = threadIdx.x;
    int ci  = blockIdx.x;
    int b   = ci / NCLS;
    int c   = ci % NCLS;

    if (tid == 0) s_n = 0;
    __syncthreads();

    // filter staged keys by threshold bucket
    int m  = g_bcnt[ci];
    u32 tb = g_tb[b];
    for (int i = tid; i < m; i += 128) {
        u64 k = g_bstage[(size_t)ci * BCAP + i];
        if ((((u32)(k >> 10)) >> 19) >= tb) {
            int p = atomicAdd(&s_n, 1);
            skey[p] = k;
        }
    }
    __syncthreads();
    int n = s_n;
    if (tid == 0) g_bcnt[ci] = 0;          // cleanup for next invocation
    if (n == 0) return;                    // uniform branch

    // pad to pow2, bitonic sort descending (score, ~boxidx)
    int P = 32; while (P < n) P <<= 1;
    for (int e = tid; e < P; e += 128) if (e >= n) skey[e] = 0ull;
    for (unsigned k = 2; k <= (unsigned)P; k <<= 1) {
        for (unsigned j = k >> 1; j > 0; j >>= 1) {
            __syncthreads();
            for (int e = tid; e < P; e += 128) {
                int ixj = e ^ (int)j;
                if (ixj > e) {
                    u64 va = skey[e], vb = skey[ixj];
                    bool desc = ((e & (int)k) == 0);
                    if (desc ? (va < vb) : (va > vb)) { skey[e] = vb; skey[ixj] = va; }
                }
            }
        }
    }
    __syncthreads();

    // decode boxes (rank order)
    float hmax = info[b * 5 + 0] - 1.f;
    float wmax = info[b * 5 + 1] - 1.f;
    for (int i = tid; i < n; i += 128) {
        u64 k = skey[i];
        int nb = 1023 - (int)(k & 0x3FFull);
        float4 a = *(const float4*)(anc + (size_t)(b * NBOX + nb) * 4);
        float ha  = a.z - a.x + 1.f;
        float wa  = a.w - a.y + 1.f;
        float cya = a.x + 0.5f * ha;
        float cxa = a.y + 0.5f * wa;
        float4 e = *(const float4*)(box + ((size_t)(b * NBOX + nb) * 81 + (c + 1)) * 4);
        float cy = (e.x / 10.f) * ha + cya;
        float cx = (e.y / 10.f) * wa + cxa;
        float h  = expf(e.z / 5.f) * ha;
        float wd = expf(e.w / 5.f) * wa;
        float ymin = fminf(fmaxf(cy - 0.5f * h,        0.f), hmax);
        float ymax = fminf(fmaxf(cy + 0.5f * h - 1.f,  0.f), hmax);
        float xmin = fminf(fmaxf(cx - 0.5f * wd,       0.f), wmax);
        float xmax = fminf(fmaxf(cx + 0.5f * wd - 1.f, 0.f), wmax);
        sbx[i]   = make_float4(ymin, xmin, ymax, xmax);
        sflag[i] = 0;
    }
    __syncthreads();

    // greedy NMS: warp 0, serial over i, j-parallel over lanes
    if (tid < 32) {
        for (int i = 0; i < n - 1; i++) {
            if (sflag[i] == 0) {
                float4 B = sbx[i];
                float ai = (B.z - B.x) * (B.w - B.y);
                for (int j = i + 1 + tid; j < n; j += 32) {
                    float4 C = sbx[j];
                    float iy = fmaxf(0.f, fminf(B.z, C.z) - fmaxf(B.x, C.x));
                    float ix = fmaxf(0.f, fminf(B.w, C.w) - fmaxf(B.y, C.y));
                    float inter = iy * ix;
                    float aj  = (C.z - C.x) * (C.w - C.y);
                    float iou = inter / fmaxf(ai + aj - inter, 1e-8f);  // exact ref
                    if (iou > 0.5f) sflag[j] = 1;
                }
            }
            __syncwarp();
        }
    }
    __syncthreads();

    // reserve global survivor slots
    if (tid == 0) s_cnt = 0;
    __syncthreads();
    int my = 0;
    for (int e = tid; e < n; e += 128) if (!sflag[e]) my++;
    if (my) atomicAdd(&s_cnt, my);
    __syncthreads();
    if (tid == 0) s_base = atomicAdd(&g_scnt2[b], s_cnt);
    __syncthreads();
    if (tid == 0) s_cnt = 0;
    __syncthreads();

    // emit survivors: key (score desc, (c,rank) asc proxy), box, histogram
    for (int e = tid; e < n; e += 128) {
        if (!sflag[e]) {
            u32 sb   = (u32)(skey[e] >> 10);
            u32 flat = (u32)(c * BCAP + e);            // rank == true class rank
            int slot = atomicAdd(&s_cnt, 1);
            g_surv[b * CAND + s_base + slot] =
                ((u64)sb << 18) | (u64)(0x3FFFFu ^ flat);
            g_cbox[(size_t)ci * BCAP + e] = sbx[e];
            atomicAdd(&g_hist2[b * NHIST + (sb >> 19)], 1u);
        }
    }
}

// ---------------------------------------------------------------------------
// K4: per batch — survivor threshold for top-100, small sort, emit output.
// grid = BATCH, block = 1024.
// ---------------------------------------------------------------------------
__global__ __launch_bounds__(1024) void final_kernel(float* __restrict__ out) {
    __shared__ u64 skey[CAND];
    __shared__ u32 wtot[32], cexc[32];
    __shared__ int s_t1, s_cnt2, s_n;

    int tid  = threadIdx.x;
    int w    = tid >> 5;
    int lane = tid & 31;
    int b    = blockIdx.x;

    if (tid == 0) { s_t1 = 0; s_n = 0; s_cnt2 = 0; }
    __syncthreads();

    // suffix scan of survivor-score histogram
    u32 h0 = g_hist2[b * NHIST + 4 * tid + 0];
    u32 h1 = g_hist2[b * NHIST + 4 * tid + 1];
    u32 h2 = g_hist2[b * NHIST + 4 * tid + 2];
    u32 h3 = g_hist2[b * NHIST + 4 * tid + 3];
    u32 s3 = h3, s2 = h2 + s3, s1 = h1 + s2, s0 = h0 + s1;

    u32 x = s0;
    #pragma unroll
    for (int off = 1; off < 32; off <<= 1) {
        u32 t = __shfl_down_sync(0xffffffffu, x, off);
        if (lane + off < 32) x += t;
    }
    if (lane == 0) wtot[w] = x;
    __syncthreads();
    if (w == 0) {
        u32 y = wtot[lane];
        u32 yi = y;
        #pragma unroll
        for (int off = 1; off < 32; off <<= 1) {
            u32 t = __shfl_down_sync(0xffffffffu, yi, off);
            if (lane + off < 32) yi += t;
        }
        cexc[lane] = yi - y;
    }
    __syncthreads();
    u32 tail = (x - s0) + cexc[w];
    u32 suf[4] = { s0 + tail, s1 + tail, s2 + tail, s3 + tail };
    #pragma unroll
    for (int q = 0; q < 4; q++) {
        int v = 4 * tid + q;
        if (suf[q] >= NCAND) atomicMax(&s_t1, v);   // highest bucket keeping >=100
    }
    __syncthreads();
    #pragma unroll
    for (int q = 0; q < 4; q++)
        if (4 * tid + q == s_t1) s_cnt2 = (int)suf[q];
    __syncthreads();

    u32 tb2 = (u32)s_t1;

    // filter survivors above the bucket threshold
    int tot = g_scnt2[b];
    for (int i = tid; i < tot; i += 1024) {
        u64 k = g_surv[b * CAND + i];
        if ((((u32)(k >> 18)) >> 19) >= tb2) {
            int p = atomicAdd(&s_n, 1);
            skey[p] = k;
        }
    }
    __syncthreads();
    int n = s_n;                                    // == s_cnt2; typ ~100-200

    int P = 128; while (P < n) P <<= 1;             // <= CAND
    for (int e = tid; e < P; e += 1024) if (e >= n) skey[e] = 0ull;
    for (unsigned k = 2; k <= (unsigned)P; k <<= 1) {
        for (unsigned j = k >> 1; j > 0; j >>= 1) {
            __syncthreads();
            for (int e = tid; e < P; e += 1024) {
                int ixj = e ^ (int)j;
                if (ixj > e) {
                    u64 va = skey[e], vb = skey[ixj];
                    bool desc = ((e & (int)k) == 0);
                    if (desc ? (va < vb) : (va > vb)) { skey[e] = vb; skey[ixj] = va; }
                }
            }
        }
    }
    __syncthreads();

    // emit top-100
    if (tid < NCAND) {
        u64 kv   = skey[tid];
        u32 sb   = (u32)(kv >> 18);
        u32 flat = 0x3FFFFu ^ ((u32)kv & 0x3FFFFu);
        int c    = (int)(flat >> 10);
        int rank = (int)(flat & (BCAP - 1));
        float4 bx = g_cbox[(size_t)(b * NCLS + c) * BCAP + rank];
        float* o = out + (size_t)(b * NCAND + tid) * 6;
        o[0] = bx.x; o[1] = bx.y; o[2] = bx.z; o[3] = bx.w;
        o[4] = __uint_as_float(sb);
        o[5] = (float)(c + 1);
    }

    // cleanup for next invocation
    g_hist2[b * NHIST + 4 * tid + 0] = 0;
    g_hist2[b * NHIST + 4 * tid + 1] = 0;
    g_hist2[b * NHIST + 4 * tid + 2] = 0;
    g_hist2[b * NHIST + 4 * tid + 3] = 0;
    if (tid == 0) g_scnt2[b] = 0;
}

// ---------------------------------------------------------------------------
extern "C" void kernel_launch(void* const* d_in, const int* in_sizes, int n_in,
                              void* d_out, int out_size) {
    const float* cls  = (const float*)d_in[0];
    const float* box  = (const float*)d_in[1];
    const float* anc  = (const float*)d_in[2];
    const float* info = (const float*)d_in[3];

    score_kernel<<<(BATCH * NBOX * 32 + 255) / 256, 256>>>(cls);
    thresh_kernel<<<BATCH, 1024>>>();
    class_nms_kernel<<<BATCH * NCLS, 128>>>(box, anc, info);
    final_kernel<<<BATCH, 1024>>>((float*)d_out);
}